// round 16
// baseline (speedup 1.0000x reference)
#include <cuda_runtime.h>
#include <cuda_bf16.h>
#include <math.h>
#include <stdint.h>

// Problem constants
#define BB   2
#define SS   2048
#define DD   1024
#define HH   16
#define DHH  64
#define INNER 2730
#define INNERP 2752               // padded to multiple of 64
#define ROWS_TOT (BB*SS)          // 4096
#define MODW 6144                 // 6*D
#define NFI  5460                 // 2*INNER
#define NFIP 5504                 // padded rows for Wt_fi

// ---------------- scratch buffers (device globals; no allocation) ----------
__device__ float g_mod [BB * MODW];
__device__ float g_qkv [(size_t)ROWS_TOT * 3 * DD];
__device__ float g_proj[(size_t)ROWS_TOT * DD];
__device__ float g_tok2[(size_t)ROWS_TOT * DD];
__device__ float g_h   [(size_t)ROWS_TOT * 2 * INNER];
__device__ __nv_bfloat16 g_xb   [(size_t)ROWS_TOT * DD];
__device__ __nv_bfloat16 g_attnb[(size_t)ROWS_TOT * DD];
__device__ __nv_bfloat16 g_ub   [(size_t)ROWS_TOT * INNERP];
// transposed bf16 weights [N, K] (K-major)
__device__ __nv_bfloat16 g_wqkv_t[(size_t)3 * DD * DD];
__device__ __nv_bfloat16 g_wao_t [(size_t)DD * DD];
__device__ __nv_bfloat16 g_wfi_t [(size_t)NFIP * DD];
__device__ __nv_bfloat16 g_wfo_t [(size_t)DD * INNERP];

// ---------------- asm helpers ------------------------------------------------
#define CP_ASYNC16(dst, src) \
    asm volatile("cp.async.cg.shared.global [%0], [%1], 16;" \
                 :: "r"(dst), "l"(src) : "memory")
#define CP_COMMIT() asm volatile("cp.async.commit_group;" ::: "memory")
#define CP_WAIT0()  asm volatile("cp.async.wait_group 0;" ::: "memory")

#define LDMX4(r0, r1, r2, r3, a) \
    asm volatile("ldmatrix.sync.aligned.m8n8.x4.shared.b16 {%0,%1,%2,%3}, [%4];" \
                 : "=r"(r0), "=r"(r1), "=r"(r2), "=r"(r3) : "r"(a))

#define MMA_BF16(d, a, b)                                                     \
    asm volatile(                                                             \
        "mma.sync.aligned.m16n8k16.row.col.f32.bf16.bf16.f32 "                \
        "{%0,%1,%2,%3}, {%4,%5,%6,%7}, {%8,%9}, {%0,%1,%2,%3};"               \
        : "+f"((d)[0]), "+f"((d)[1]), "+f"((d)[2]), "+f"((d)[3])              \
        : "r"((a)[0]), "r"((a)[1]), "r"((a)[2]), "r"((a)[3]),                 \
          "r"((b)[0]), "r"((b)[1]))

__device__ __forceinline__ uint32_t smem_addr(const void* p) {
    return (uint32_t)__cvta_generic_to_shared(p);
}

// ---------------- bf16 mma.sync GEMM -----------------------------------------
// C[M,N] = A[M,K]bf16 @ Bt[N,K]bf16^T + bias,  f32 accum
// CTA tile 128x128, BK=32, 8 warps (4x2), warp tile 32x64, mma.m16n8k16.
// smem rows: 16 words (32 bf16) padded to stride 20 -> conflict-free for both
// cp.async stores (16B aligned: 80r+16q) and ldmatrix (20r mod 32 covers all
// 32 banks over any 8 consecutive rows).
#define ASTR 20
#define STGB (128 * ASTR * 4)     // 10240 bytes per stage per matrix

__global__ __launch_bounds__(256, 2) void bf16_gemm_bias(
    const __nv_bfloat16* __restrict__ A, const __nv_bfloat16* __restrict__ Bt,
    const float* __restrict__ bias, float* __restrict__ C, int N, int K)
{
    __shared__ unsigned As[2][128 * ASTR];
    __shared__ unsigned Bs[2][128 * ASTR];

    const int tid  = threadIdx.x;
    const int lane = tid & 31, wid = tid >> 5;
    const int g    = lane >> 2, t = lane & 3;
    const int wm   = wid & 3;        // warp M idx (32 rows)
    const int wn   = wid >> 2;       // warp N idx (64 cols)
    const int row0 = blockIdx.y * 128;
    const int col0 = blockIdx.x * 128;

    const uint32_t sA = smem_addr(&As[0][0]);
    const uint32_t sB = smem_addr(&Bs[0][0]);

    // cp.async thread mapping: 2 segments per thread per matrix per chunk
    const int ldr = tid >> 1;                 // rows: thread covers r, r+128? no:
    // p = tid + i*256 ; r = p>>2 ; q = p&3
    // ldmatrix per-lane address offsets (bytes), lane-fixed parts:
    const int aRow = wm * 32 + ((lane >> 3) & 1) * 8 + (lane & 7);
    const int aColW = (lane >> 4) * 4;                   // 0 or 4
    const uint32_t aOff = (uint32_t)(aRow * ASTR + aColW) * 4;
    const int bRow = wn * 64 + (lane >> 4) * 8 + (lane & 7);
    const int bColW = ((lane >> 3) & 1) * 4;
    const uint32_t bOff = (uint32_t)(bRow * ASTR + bColW) * 4;
    (void)ldr;

    float acc[2][8][4];
    #pragma unroll
    for (int i = 0; i < 2; i++)
        #pragma unroll
        for (int j = 0; j < 8; j++)
            #pragma unroll
            for (int q = 0; q < 4; q++) acc[i][j][q] = 0.f;

    auto load_stage = [&](int chunk, int buf) {
        const int kt = chunk << 5;
        #pragma unroll
        for (int i = 0; i < 2; i++) {
            int p = tid + i * 256;
            int r = p >> 2, q = p & 3;
            uint32_t off = (uint32_t)(r * ASTR + q * 4) * 4 + buf * STGB;
            CP_ASYNC16(sA + off, A  + (size_t)(row0 + r) * K + kt + q * 8);
            CP_ASYNC16(sB + off, Bt + (size_t)(col0 + r) * K + kt + q * 8);
        }
        CP_COMMIT();
    };

    load_stage(0, 0);

    const int nk = K >> 5;           // K multiple of 32
    for (int c = 0; c < nk; c++) {
        const int buf = c & 1;
        CP_WAIT0();
        __syncthreads();
        if (c + 1 < nk) load_stage(c + 1, buf ^ 1);

        const uint32_t aBase = sA + buf * STGB + aOff;
        const uint32_t bBase = sB + buf * STGB + bOff;
        #pragma unroll
        for (int ks = 0; ks < 2; ks++) {
            unsigned af[2][4], bfr[8][2];
            #pragma unroll
            for (int mt = 0; mt < 2; mt++)
                LDMX4(af[mt][0], af[mt][1], af[mt][2], af[mt][3],
                      aBase + mt * (16 * ASTR * 4) + ks * 32);
            #pragma unroll
            for (int pn = 0; pn < 4; pn++)
                LDMX4(bfr[2 * pn][0], bfr[2 * pn][1],
                      bfr[2 * pn + 1][0], bfr[2 * pn + 1][1],
                      bBase + pn * (16 * ASTR * 4) + ks * 32);
            #pragma unroll
            for (int mt = 0; mt < 2; mt++)
                #pragma unroll
                for (int nt = 0; nt < 8; nt++)
                    MMA_BF16(acc[mt][nt], af[mt], bfr[nt]);
        }
        __syncthreads();
    }

    // epilogue: bias + store (float2); acc c0,c1 = row g; c2,c3 = row g+8
    #pragma unroll
    for (int mt = 0; mt < 2; mt++) {
        int r = row0 + wm * 32 + mt * 16 + g;
        #pragma unroll
        for (int nt = 0; nt < 8; nt++) {
            int c = col0 + wn * 64 + nt * 8 + t * 2;
            if (c < N) {
                float bc0 = bias[c], bc1 = bias[c + 1];
                float2 v0 = make_float2(acc[mt][nt][0] + bc0, acc[mt][nt][1] + bc1);
                float2 v1 = make_float2(acc[mt][nt][2] + bc0, acc[mt][nt][3] + bc1);
                *(float2*)&C[(size_t)r * N + c]       = v0;
                *(float2*)&C[(size_t)(r + 8) * N + c] = v1;
            }
        }
    }
}

// -------- weight transpose + bf16 convert: out[n*Kp+k] = bf16(in[k*N+n]) ----
__global__ __launch_bounds__(256) void transpose_w(
    const float* __restrict__ in, __nv_bfloat16* __restrict__ out,
    int K, int N, int Kp)
{
    __shared__ float t[32][33];
    int n0 = blockIdx.x * 32, k0 = blockIdx.y * 32;
    int tx = threadIdx.x & 31, ty = threadIdx.x >> 5;
    #pragma unroll
    for (int j = 0; j < 4; j++) {
        int k = k0 + ty + j * 8, n = n0 + tx;
        t[ty + j * 8][tx] = (k < K && n < N) ? in[(size_t)k * N + n] : 0.f;
    }
    __syncthreads();
    #pragma unroll
    for (int j = 0; j < 4; j++) {
        int n = n0 + ty + j * 8, k = k0 + tx;
        out[(size_t)n * Kp + k] = __float2bfloat16(t[tx][ty + j * 8]);
    }
}

// ---------------- mod = silu(cond) @ w_mod + b_mod --------------------------
__global__ __launch_bounds__(256) void mod_kernel(
    const float* __restrict__ cond, const float* __restrict__ w,
    const float* __restrict__ b, float* __restrict__ mod)
{
    __shared__ float sc[DD];
    int bb = blockIdx.y;
    for (int i = threadIdx.x; i < DD; i += 256) {
        float v = cond[bb * DD + i];
        sc[i] = v / (1.f + __expf(-v));
    }
    __syncthreads();
    int col = blockIdx.x * 256 + threadIdx.x;
    float a0 = 0.f, a1 = 0.f, a2 = 0.f, a3 = 0.f;
    #pragma unroll 4
    for (int i = 0; i < DD; i += 4) {
        a0 += sc[i    ] * w[(size_t)(i    ) * MODW + col];
        a1 += sc[i + 1] * w[(size_t)(i + 1) * MODW + col];
        a2 += sc[i + 2] * w[(size_t)(i + 2) * MODW + col];
        a3 += sc[i + 3] * w[(size_t)(i + 3) * MODW + col];
    }
    mod[bb * MODW + col] = a0 + a1 + a2 + a3 + b[col];
}

// ---------------- LayerNorm + modulate (bf16 output) ------------------------
__global__ __launch_bounds__(256) void ln_mod_kernel(
    const float* __restrict__ x, const float* __restrict__ mod,
    __nv_bfloat16* __restrict__ y, int shift_off, int scale_off)
{
    int row = blockIdx.x;
    int b = row >> 11;
    const float* xr = x + (size_t)row * DD;
    float s = 0.f, s2 = 0.f;
    for (int i = threadIdx.x; i < DD; i += 256) {
        float v = xr[i]; s += v; s2 += v * v;
    }
    #pragma unroll
    for (int o = 16; o; o >>= 1) {
        s  += __shfl_xor_sync(~0u, s,  o);
        s2 += __shfl_xor_sync(~0u, s2, o);
    }
    __shared__ float rs[8], rs2[8];
    int w = threadIdx.x >> 5, lane = threadIdx.x & 31;
    if (lane == 0) { rs[w] = s; rs2[w] = s2; }
    __syncthreads();
    if (threadIdx.x == 0) {
        float a = 0.f, a2 = 0.f;
        #pragma unroll
        for (int i = 0; i < 8; i++) { a += rs[i]; a2 += rs2[i]; }
        rs[0] = a; rs2[0] = a2;
    }
    __syncthreads();
    float mean = rs[0] * (1.f / DD);
    float var  = rs2[0] * (1.f / DD) - mean * mean;
    float rstd = rsqrtf(var + 1e-5f);
    const float* mo = mod + b * MODW;
    __nv_bfloat16* yr = y + (size_t)row * DD;
    for (int i = threadIdx.x; i < DD; i += 256) {
        float v = (xr[i] - mean) * rstd;
        yr[i] = __float2bfloat16(v * (1.f + mo[scale_off + i]) + mo[shift_off + i]);
    }
}

// ---------------- RoPE + l2norm (in-place on q,k slices of qkv) -------------
__global__ __launch_bounds__(256) void rope_l2_kernel(float* __restrict__ qkv)
{
    int gw = (blockIdx.x * 256 + threadIdx.x) >> 5;
    int lane = threadIdx.x & 31;
    int which = gw & 1;
    int h = (gw >> 1) & (HH - 1);
    int bs = gw >> 5;
    float* base = qkv + (size_t)bs * (3 * DD) + which * DD + h * DHH;
    int pos = bs & (SS - 1);

    float2 p = reinterpret_cast<float2*>(base)[lane];
    float inv = __expf(-((float)lane * (1.f / 32.f)) * 9.210340371976184f);
    float th = (float)pos * inv;
    float sn, cs;
    sincosf(th, &sn, &cs);
    float re = p.x * cs - p.y * sn;
    float ro = p.x * sn + p.y * cs;
    float ssq = re * re + ro * ro;
    #pragma unroll
    for (int o = 16; o; o >>= 1) ssq += __shfl_xor_sync(~0u, ssq, o);
    float n = sqrtf(ssq);
    float sc = 1.f / fmaxf(n, 1e-12f);
    if (which == 0) sc *= 0.125f;
    float2 out; out.x = re * sc; out.y = ro * sc;
    reinterpret_cast<float2*>(base)[lane] = out;
}

// ---------------- Flash attention (fp32; 16 rows/CTA, warp-per-row) ---------
__global__ __launch_bounds__(512) void attn_kernel(
    const float* __restrict__ qkv, __nv_bfloat16* __restrict__ out)
{
    constexpr int RW = 16, TK = 32;
    __shared__ float Ks[TK][DHH + 1];
    __shared__ float Vs[TK][DHH + 1];
    __shared__ float Qs[RW][DHH];
    __shared__ float Ps[RW][TK];

    int w = threadIdx.x >> 5, lane = threadIdx.x & 31;
    int bid = blockIdx.x;
    int rowTile = bid & (SS / RW - 1);       // % 128
    int bh = bid >> 7;                        // / 128
    int h = bh & (HH - 1);
    int b = bh >> 4;
    int q0 = rowTile * RW;

    for (int i = threadIdx.x; i < RW * DHH; i += 512) {
        int r = i >> 6, d = i & 63;
        Qs[r][d] = qkv[((size_t)(b * SS + q0 + r)) * (3 * DD) + h * DHH + d];
    }
    __syncthreads();

    float qr[DHH];
    #pragma unroll
    for (int d = 0; d < DHH; d++) qr[d] = Qs[w][d];

    float m = -1e30f, l = 0.f, acc0 = 0.f, acc1 = 0.f;

    for (int t0 = 0; t0 < SS; t0 += TK) {
        for (int i = threadIdx.x; i < TK * DHH; i += 512) {
            int r = i >> 6, d = i & 63;
            size_t base = ((size_t)(b * SS + t0 + r)) * (3 * DD) + h * DHH + d;
            Ks[r][d] = qkv[base + DD];
            Vs[r][d] = qkv[base + 2 * DD];
        }
        __syncthreads();

        float s = 0.f;
        #pragma unroll
        for (int d = 0; d < DHH; d++) s += qr[d] * Ks[lane][d];

        float mt = s;
        #pragma unroll
        for (int o = 16; o; o >>= 1) mt = fmaxf(mt, __shfl_xor_sync(~0u, mt, o));
        float mn = fmaxf(m, mt);
        float alpha = __expf(m - mn);
        float p = __expf(s - mn);
        float ps = p;
        #pragma unroll
        for (int o = 16; o; o >>= 1) ps += __shfl_xor_sync(~0u, ps, o);
        l = l * alpha + ps;
        acc0 *= alpha; acc1 *= alpha;
        m = mn;
        Ps[w][lane] = p;
        __syncwarp();
        #pragma unroll
        for (int j = 0; j < TK; j++) {
            float pj = Ps[w][j];
            acc0 += pj * Vs[j][lane];
            acc1 += pj * Vs[j][lane + 32];
        }
        __syncthreads();
    }
    float invl = 1.f / l;
    size_t o = ((size_t)(b * SS + q0 + w)) * DD + h * DHH;
    out[o + lane]      = __float2bfloat16(acc0 * invl);
    out[o + lane + 32] = __float2bfloat16(acc1 * invl);
}

// ---------------- residual + gate -------------------------------------------
__global__ __launch_bounds__(256) void resgate_kernel(
    const float* __restrict__ base, const float* __restrict__ add,
    const float* __restrict__ mod, int goff, float* __restrict__ out)
{
    size_t i = (size_t)blockIdx.x * 256 + threadIdx.x;
    int col = (int)(i & (DD - 1));
    int row = (int)(i >> 10);
    int b = row >> 11;
    out[i] = base[i] + mod[b * MODW + goff + col] * add[i];
}

// ---------------- swiglu: u = value * silu(gate), bf16, padded stride -------
__global__ __launch_bounds__(256) void swiglu_kernel(
    const float* __restrict__ h, __nv_bfloat16* __restrict__ u)
{
    size_t i = (size_t)blockIdx.x * 256 + threadIdx.x;
    int row = (int)(i / INNERP), col = (int)(i % INNERP);
    float r = 0.f;
    if (col < INNER) {
        const float* hr = h + (size_t)row * (2 * INNER);
        float v = hr[col];
        float g = hr[INNER + col];
        r = v * (g / (1.f + __expf(-g)));
    }
    u[i] = __float2bfloat16(r);
}

// ---------------- launch ----------------------------------------------------
extern "C" void kernel_launch(void* const* d_in, const int* in_sizes, int n_in,
                              void* d_out, int out_size)
{
    const float* tokens = (const float*)d_in[0];
    const float* cond   = (const float*)d_in[1];
    const float* w_qkv  = (const float*)d_in[2];
    const float* b_qkv  = (const float*)d_in[3];
    const float* w_ao   = (const float*)d_in[4];
    const float* b_ao   = (const float*)d_in[5];
    const float* w_fi   = (const float*)d_in[6];
    const float* b_fi   = (const float*)d_in[7];
    const float* w_fo   = (const float*)d_in[8];
    const float* b_fo   = (const float*)d_in[9];
    const float* w_mod  = (const float*)d_in[10];
    const float* b_mod  = (const float*)d_in[11];
    float* out = (float*)d_out;

    float *mod, *qkv, *proj, *tok2, *hbuf;
    __nv_bfloat16 *xb, *attnb, *ub, *wqkv_t, *wao_t, *wfi_t, *wfo_t;
    cudaGetSymbolAddress((void**)&mod,   g_mod);
    cudaGetSymbolAddress((void**)&qkv,   g_qkv);
    cudaGetSymbolAddress((void**)&proj,  g_proj);
    cudaGetSymbolAddress((void**)&tok2,  g_tok2);
    cudaGetSymbolAddress((void**)&hbuf,  g_h);
    cudaGetSymbolAddress((void**)&xb,    g_xb);
    cudaGetSymbolAddress((void**)&attnb, g_attnb);
    cudaGetSymbolAddress((void**)&ub,    g_ub);
    cudaGetSymbolAddress((void**)&wqkv_t, g_wqkv_t);
    cudaGetSymbolAddress((void**)&wao_t,  g_wao_t);
    cudaGetSymbolAddress((void**)&wfi_t,  g_wfi_t);
    cudaGetSymbolAddress((void**)&wfo_t,  g_wfo_t);

    // 0) weight transposes -> bf16 [N, Kp]
    transpose_w<<<dim3(3 * DD / 32, DD / 32), 256>>>(w_qkv, wqkv_t, DD, 3 * DD, DD);
    transpose_w<<<dim3(DD / 32, DD / 32), 256>>>(w_ao, wao_t, DD, DD, DD);
    transpose_w<<<dim3(NFIP / 32, DD / 32), 256>>>(w_fi, wfi_t, DD, NFI, DD);
    transpose_w<<<dim3(DD / 32, INNERP / 32), 256>>>(w_fo, wfo_t, INNER, DD, INNERP);

    // 1) modulation vector
    mod_kernel<<<dim3(MODW / 256, BB), 256>>>(cond, w_mod, b_mod, mod);
    // 2) x = modulate(LN(tokens)) -> bf16
    ln_mod_kernel<<<ROWS_TOT, 256>>>(tokens, mod, xb, 0, 1024);
    // 3) qkv (bf16 mma + ldmatrix + cp.async)
    bf16_gemm_bias<<<dim3(3 * DD / 128, ROWS_TOT / 128), 256>>>(
        xb, wqkv_t, b_qkv, qkv, 3 * DD, DD);
    // 4) rope + l2norm
    rope_l2_kernel<<<(BB * SS * HH * 2) / 8, 256>>>(qkv);
    // 5) attention -> bf16
    attn_kernel<<<BB * HH * (SS / 16), 512>>>(qkv, attnb);
    // 6) attn out projection
    bf16_gemm_bias<<<dim3(DD / 128, ROWS_TOT / 128), 256>>>(
        attnb, wao_t, b_ao, proj, DD, DD);
    // 7) tokens2 = tokens + gate_a * proj
    resgate_kernel<<<ROWS_TOT * DD / 256, 256>>>(tokens, proj, mod, 2048, tok2);
    // 8) y = modulate(LN(tokens2)) -> bf16 (reuse xb)
    ln_mod_kernel<<<ROWS_TOT, 256>>>(tok2, mod, xb, 3072, 4096);
    // 9) ffn_in, N=5460 (Bt padded to 5504 rows)
    bf16_gemm_bias<<<dim3(NFIP / 128, ROWS_TOT / 128), 256>>>(
        xb, wfi_t, b_fi, hbuf, NFI, DD);
    // 10) swiglu -> bf16 padded to 2752
    swiglu_kernel<<<(unsigned)(((size_t)ROWS_TOT * INNERP) / 256), 256>>>(hbuf, ub);
    // 11) ffn_out, K = 2752 (zero-padded)
    bf16_gemm_bias<<<dim3(DD / 128, ROWS_TOT / 128), 256>>>(
        ub, wfo_t, b_fo, proj, DD, INNERP);
    // 12) out = tokens2 + gate_m * proj
    resgate_kernel<<<ROWS_TOT * DD / 256, 256>>>(tok2, proj, mod, 5120, out);
}

// round 17
// speedup vs baseline: 1.2800x; 1.2800x over previous
#include <cuda_runtime.h>
#include <cuda_bf16.h>
#include <math.h>
#include <stdint.h>

// Problem constants
#define BB   2
#define SS   2048
#define DD   1024
#define HH   16
#define DHH  64
#define INNER 2730
#define INNERP 2752               // padded to multiple of 64
#define ROWS_TOT (BB*SS)          // 4096
#define MODW 6144                 // 6*D
#define NFI  5460                 // 2*INNER
#define NFIP 5504                 // padded rows for Wt_fi

// ---------------- scratch buffers (device globals; no allocation) ----------
__device__ float g_mod [BB * MODW];
__device__ float g_qkv [(size_t)ROWS_TOT * 3 * DD];
__device__ float g_proj[(size_t)ROWS_TOT * DD];
__device__ float g_tok2[(size_t)ROWS_TOT * DD];
__device__ float g_h   [(size_t)ROWS_TOT * 2 * INNER];
__device__ __nv_bfloat16 g_xb   [(size_t)ROWS_TOT * DD];
__device__ __nv_bfloat16 g_attnb[(size_t)ROWS_TOT * DD];
__device__ __nv_bfloat16 g_ub   [(size_t)ROWS_TOT * INNERP];
// transposed bf16 weights [N, K] (K-major)
__device__ __nv_bfloat16 g_wqkv_t[(size_t)3 * DD * DD];
__device__ __nv_bfloat16 g_wao_t [(size_t)DD * DD];
__device__ __nv_bfloat16 g_wfi_t [(size_t)NFIP * DD];
__device__ __nv_bfloat16 g_wfo_t [(size_t)DD * INNERP];

// ---------------- asm helpers ------------------------------------------------
#define CP_ASYNC16(dst, src) \
    asm volatile("cp.async.cg.shared.global [%0], [%1], 16;" \
                 :: "r"(dst), "l"(src) : "memory")
#define CP_COMMIT() asm volatile("cp.async.commit_group;" ::: "memory")
#define CP_WAIT1()  asm volatile("cp.async.wait_group 1;" ::: "memory")

#define LDMX4(r0, r1, r2, r3, a) \
    asm volatile("ldmatrix.sync.aligned.m8n8.x4.shared.b16 {%0,%1,%2,%3}, [%4];" \
                 : "=r"(r0), "=r"(r1), "=r"(r2), "=r"(r3) : "r"(a))

#define MMA_BF16(d, a, b)                                                     \
    asm volatile(                                                             \
        "mma.sync.aligned.m16n8k16.row.col.f32.bf16.bf16.f32 "                \
        "{%0,%1,%2,%3}, {%4,%5,%6,%7}, {%8,%9}, {%0,%1,%2,%3};"               \
        : "+f"((d)[0]), "+f"((d)[1]), "+f"((d)[2]), "+f"((d)[3])              \
        : "r"((a)[0]), "r"((a)[1]), "r"((a)[2]), "r"((a)[3]),                 \
          "r"((b)[0]), "r"((b)[1]))

__device__ __forceinline__ uint32_t smem_addr(const void* p) {
    return (uint32_t)__cvta_generic_to_shared(p);
}

// ---------------- bf16 mma.sync GEMM, 3-stage cp.async pipeline -------------
// C[M,N] = A[M,K]bf16 @ Bt[N,K]bf16^T + bias,  f32 accum
// CTA 128x128, BK=32, 8 warps (4x2), warp tile 32x64, mma.m16n8k16.
// smem rows padded to stride 20 words: conflict-free for cp.async stores
// and ldmatrix reads. 3 stages x (A+B) x 10240B = 61440B dynamic smem.
#define ASTR 20
#define STGW (128 * ASTR)         // words per stage per matrix
#define STGB (STGW * 4)           // 10240 bytes
#define GSMEM (3 * 2 * STGB)      // 61440

__global__ __launch_bounds__(256) void bf16_gemm_bias(
    const __nv_bfloat16* __restrict__ A, const __nv_bfloat16* __restrict__ Bt,
    const float* __restrict__ bias, float* __restrict__ C, int N, int K)
{
    extern __shared__ unsigned dynsm[];
    unsigned* Asm = dynsm;                 // 3 stages
    unsigned* Bsm = dynsm + 3 * STGW;      // 3 stages

    const int tid  = threadIdx.x;
    const int lane = tid & 31, wid = tid >> 5;
    const int g    = lane >> 2, t = lane & 3;
    const int wm   = wid & 3;
    const int wn   = wid >> 2;
    const int row0 = blockIdx.y * 128;
    const int col0 = blockIdx.x * 128;

    const uint32_t sA = smem_addr(Asm);
    const uint32_t sB = smem_addr(Bsm);

    // ldmatrix lane-fixed byte offsets
    const int aRow = wm * 32 + ((lane >> 3) & 1) * 8 + (lane & 7);
    const uint32_t aOff = (uint32_t)(aRow * ASTR + (lane >> 4) * 4) * 4;
    const int bRow = wn * 64 + (lane >> 4) * 8 + (lane & 7);
    const uint32_t bOff = (uint32_t)(bRow * ASTR + ((lane >> 3) & 1) * 4) * 4;

    float acc[2][8][4];
    #pragma unroll
    for (int i = 0; i < 2; i++)
        #pragma unroll
        for (int j = 0; j < 8; j++)
            #pragma unroll
            for (int q = 0; q < 4; q++) acc[i][j][q] = 0.f;

    auto load_stage = [&](int chunk, int buf) {
        const int kt = chunk << 5;
        #pragma unroll
        for (int i = 0; i < 2; i++) {
            int p = tid + i * 256;
            int r = p >> 2, q = p & 3;
            uint32_t off = (uint32_t)(r * ASTR + q * 4) * 4 + buf * STGB;
            CP_ASYNC16(sA + off, A  + (size_t)(row0 + r) * K + kt + q * 8);
            CP_ASYNC16(sB + off, Bt + (size_t)(col0 + r) * K + kt + q * 8);
        }
        CP_COMMIT();
    };

    const int nk = K >> 5;
    load_stage(0, 0);
    load_stage(1, 1);

    int buf = 0;
    for (int c = 0; c < nk; c++) {
        CP_WAIT1();                 // stage c resident (groups complete in order)
        __syncthreads();

        const uint32_t aBase = sA + buf * STGB + aOff;
        const uint32_t bBase = sB + buf * STGB + bOff;
        #pragma unroll
        for (int ks = 0; ks < 2; ks++) {
            unsigned af[2][4], bfr[8][2];
            #pragma unroll
            for (int mt = 0; mt < 2; mt++)
                LDMX4(af[mt][0], af[mt][1], af[mt][2], af[mt][3],
                      aBase + mt * (16 * ASTR * 4) + ks * 32);
            #pragma unroll
            for (int pn = 0; pn < 4; pn++)
                LDMX4(bfr[2 * pn][0], bfr[2 * pn][1],
                      bfr[2 * pn + 1][0], bfr[2 * pn + 1][1],
                      bBase + pn * (16 * ASTR * 4) + ks * 32);
            #pragma unroll
            for (int mt = 0; mt < 2; mt++)
                #pragma unroll
                for (int nt = 0; nt < 8; nt++)
                    MMA_BF16(acc[mt][nt], af[mt], bfr[nt]);
        }

        if (c + 2 < nk) {
            int nb = buf + 2; if (nb >= 3) nb -= 3;
            load_stage(c + 2, nb);   // overwrites stage consumed in iter c-1: safe
        }
        if (++buf == 3) buf = 0;
    }

    // epilogue: bias + store (float2)
    #pragma unroll
    for (int mt = 0; mt < 2; mt++) {
        int r = row0 + wm * 32 + mt * 16 + g;
        #pragma unroll
        for (int nt = 0; nt < 8; nt++) {
            int c = col0 + wn * 64 + nt * 8 + t * 2;
            if (c < N) {
                float bc0 = bias[c], bc1 = bias[c + 1];
                float2 v0 = make_float2(acc[mt][nt][0] + bc0, acc[mt][nt][1] + bc1);
                float2 v1 = make_float2(acc[mt][nt][2] + bc0, acc[mt][nt][3] + bc1);
                *(float2*)&C[(size_t)r * N + c]       = v0;
                *(float2*)&C[(size_t)(r + 8) * N + c] = v1;
            }
        }
    }
}

// -------- weight transpose + bf16 convert: out[n*Kp+k] = bf16(in[k*N+n]) ----
__global__ __launch_bounds__(256) void transpose_w(
    const float* __restrict__ in, __nv_bfloat16* __restrict__ out,
    int K, int N, int Kp)
{
    __shared__ float t[32][33];
    int n0 = blockIdx.x * 32, k0 = blockIdx.y * 32;
    int tx = threadIdx.x & 31, ty = threadIdx.x >> 5;
    #pragma unroll
    for (int j = 0; j < 4; j++) {
        int k = k0 + ty + j * 8, n = n0 + tx;
        t[ty + j * 8][tx] = (k < K && n < N) ? in[(size_t)k * N + n] : 0.f;
    }
    __syncthreads();
    #pragma unroll
    for (int j = 0; j < 4; j++) {
        int n = n0 + ty + j * 8, k = k0 + tx;
        out[(size_t)n * Kp + k] = __float2bfloat16(t[tx][ty + j * 8]);
    }
}

// ---------------- mod = silu(cond) @ w_mod + b_mod --------------------------
__global__ __launch_bounds__(256) void mod_kernel(
    const float* __restrict__ cond, const float* __restrict__ w,
    const float* __restrict__ b, float* __restrict__ mod)
{
    __shared__ float sc[DD];
    int bb = blockIdx.y;
    for (int i = threadIdx.x; i < DD; i += 256) {
        float v = cond[bb * DD + i];
        sc[i] = v / (1.f + __expf(-v));
    }
    __syncthreads();
    int col = blockIdx.x * 256 + threadIdx.x;
    float a0 = 0.f, a1 = 0.f, a2 = 0.f, a3 = 0.f;
    #pragma unroll 4
    for (int i = 0; i < DD; i += 4) {
        a0 += sc[i    ] * w[(size_t)(i    ) * MODW + col];
        a1 += sc[i + 1] * w[(size_t)(i + 1) * MODW + col];
        a2 += sc[i + 2] * w[(size_t)(i + 2) * MODW + col];
        a3 += sc[i + 3] * w[(size_t)(i + 3) * MODW + col];
    }
    mod[bb * MODW + col] = a0 + a1 + a2 + a3 + b[col];
}

// ---------------- LayerNorm + modulate (bf16 output) ------------------------
__global__ __launch_bounds__(256) void ln_mod_kernel(
    const float* __restrict__ x, const float* __restrict__ mod,
    __nv_bfloat16* __restrict__ y, int shift_off, int scale_off)
{
    int row = blockIdx.x;
    int b = row >> 11;
    const float* xr = x + (size_t)row * DD;
    float s = 0.f, s2 = 0.f;
    for (int i = threadIdx.x; i < DD; i += 256) {
        float v = xr[i]; s += v; s2 += v * v;
    }
    #pragma unroll
    for (int o = 16; o; o >>= 1) {
        s  += __shfl_xor_sync(~0u, s,  o);
        s2 += __shfl_xor_sync(~0u, s2, o);
    }
    __shared__ float rs[8], rs2[8];
    int w = threadIdx.x >> 5, lane = threadIdx.x & 31;
    if (lane == 0) { rs[w] = s; rs2[w] = s2; }
    __syncthreads();
    if (threadIdx.x == 0) {
        float a = 0.f, a2 = 0.f;
        #pragma unroll
        for (int i = 0; i < 8; i++) { a += rs[i]; a2 += rs2[i]; }
        rs[0] = a; rs2[0] = a2;
    }
    __syncthreads();
    float mean = rs[0] * (1.f / DD);
    float var  = rs2[0] * (1.f / DD) - mean * mean;
    float rstd = rsqrtf(var + 1e-5f);
    const float* mo = mod + b * MODW;
    __nv_bfloat16* yr = y + (size_t)row * DD;
    for (int i = threadIdx.x; i < DD; i += 256) {
        float v = (xr[i] - mean) * rstd;
        yr[i] = __float2bfloat16(v * (1.f + mo[scale_off + i]) + mo[shift_off + i]);
    }
}

// ---------------- RoPE + l2norm (in-place on q,k slices of qkv) -------------
__global__ __launch_bounds__(256) void rope_l2_kernel(float* __restrict__ qkv)
{
    int gw = (blockIdx.x * 256 + threadIdx.x) >> 5;
    int lane = threadIdx.x & 31;
    int which = gw & 1;
    int h = (gw >> 1) & (HH - 1);
    int bs = gw >> 5;
    float* base = qkv + (size_t)bs * (3 * DD) + which * DD + h * DHH;
    int pos = bs & (SS - 1);

    float2 p = reinterpret_cast<float2*>(base)[lane];
    float inv = __expf(-((float)lane * (1.f / 32.f)) * 9.210340371976184f);
    float th = (float)pos * inv;
    float sn, cs;
    sincosf(th, &sn, &cs);
    float re = p.x * cs - p.y * sn;
    float ro = p.x * sn + p.y * cs;
    float ssq = re * re + ro * ro;
    #pragma unroll
    for (int o = 16; o; o >>= 1) ssq += __shfl_xor_sync(~0u, ssq, o);
    float n = sqrtf(ssq);
    float sc = 1.f / fmaxf(n, 1e-12f);
    if (which == 0) sc *= 0.125f;
    float2 out; out.x = re * sc; out.y = ro * sc;
    reinterpret_cast<float2*>(base)[lane] = out;
}

// ---------------- Flash attention (fp32; 16 rows/CTA, warp-per-row) ---------
// K tiles staged as float2 (LDS.64), V interleaved as (v[c], v[c+32]) pairs,
// P broadcast by shfl (no Ps smem, no __syncwarp).
__global__ __launch_bounds__(512) void attn_kernel(
    const float* __restrict__ qkv, __nv_bfloat16* __restrict__ out)
{
    constexpr int RW = 16, TK = 32;
    __shared__ float2 Ks2[TK][DHH / 2 + 1];   // stride 33 float2
    __shared__ float2 Vs2[TK][32 + 1];        // Vs2[j][c] = (V[j][c], V[j][c+32])
    __shared__ float  Qs[RW][DHH];

    int w = threadIdx.x >> 5, lane = threadIdx.x & 31;
    int bid = blockIdx.x;
    int rowTile = bid & (SS / RW - 1);       // % 128
    int bh = bid >> 7;
    int h = bh & (HH - 1);
    int b = bh >> 4;
    int q0 = rowTile * RW;

    {   // Q staging: one float2 per thread
        int i = threadIdx.x;
        int r = i >> 5, d2 = (i & 31) * 2;
        float2 qv = *(const float2*)(qkv +
            ((size_t)(b * SS + q0 + r)) * (3 * DD) + h * DHH + d2);
        Qs[r][d2] = qv.x; Qs[r][d2 + 1] = qv.y;
    }
    __syncthreads();

    float qr[DHH];
    #pragma unroll
    for (int d = 0; d < DHH; d++) qr[d] = Qs[w][d];

    float m = -1e30f, l = 0.f, acc0 = 0.f, acc1 = 0.f;

    const int sr = threadIdx.x >> 4;           // 0..31 staging row
    const int sd = (threadIdx.x & 15) * 4;     // 0..60 staging col

    for (int t0 = 0; t0 < SS; t0 += TK) {
        {   // K, V staging: one float4 each per thread
            size_t base = ((size_t)(b * SS + t0 + sr)) * (3 * DD) + h * DHH + sd;
            float4 kv = *(const float4*)(qkv + base + DD);
            Ks2[sr][sd >> 1]       = make_float2(kv.x, kv.y);
            Ks2[sr][(sd >> 1) + 1] = make_float2(kv.z, kv.w);
            float4 vv = *(const float4*)(qkv + base + 2 * DD);
            if (sd < 32) {
                Vs2[sr][sd    ].x = vv.x; Vs2[sr][sd + 1].x = vv.y;
                Vs2[sr][sd + 2].x = vv.z; Vs2[sr][sd + 3].x = vv.w;
            } else {
                Vs2[sr][sd - 32].y = vv.x; Vs2[sr][sd - 31].y = vv.y;
                Vs2[sr][sd - 30].y = vv.z; Vs2[sr][sd - 29].y = vv.w;
            }
        }
        __syncthreads();

        float s = 0.f;
        #pragma unroll
        for (int d2 = 0; d2 < DHH / 2; d2++) {
            float2 kv = Ks2[lane][d2];
            s += qr[2 * d2] * kv.x + qr[2 * d2 + 1] * kv.y;
        }

        float mt = s;
        #pragma unroll
        for (int o = 16; o; o >>= 1) mt = fmaxf(mt, __shfl_xor_sync(~0u, mt, o));
        float mn = fmaxf(m, mt);
        float alpha = __expf(m - mn);
        float p = __expf(s - mn);
        float ps = p;
        #pragma unroll
        for (int o = 16; o; o >>= 1) ps += __shfl_xor_sync(~0u, ps, o);
        l = l * alpha + ps;
        acc0 *= alpha; acc1 *= alpha;
        m = mn;

        #pragma unroll
        for (int j = 0; j < TK; j++) {
            float pj = __shfl_sync(~0u, p, j);
            float2 v = Vs2[j][lane];
            acc0 += pj * v.x;
            acc1 += pj * v.y;
        }
        __syncthreads();
    }
    float invl = 1.f / l;
    size_t o = ((size_t)(b * SS + q0 + w)) * DD + h * DHH;
    out[o + lane]      = __float2bfloat16(acc0 * invl);
    out[o + lane + 32] = __float2bfloat16(acc1 * invl);
}

// ---------------- residual + gate -------------------------------------------
__global__ __launch_bounds__(256) void resgate_kernel(
    const float* __restrict__ base, const float* __restrict__ add,
    const float* __restrict__ mod, int goff, float* __restrict__ out)
{
    size_t i = (size_t)blockIdx.x * 256 + threadIdx.x;
    int col = (int)(i & (DD - 1));
    int row = (int)(i >> 10);
    int b = row >> 11;
    out[i] = base[i] + mod[b * MODW + goff + col] * add[i];
}

// ---------------- swiglu: u = value * silu(gate), bf16, padded stride -------
__global__ __launch_bounds__(256) void swiglu_kernel(
    const float* __restrict__ h, __nv_bfloat16* __restrict__ u)
{
    size_t i = (size_t)blockIdx.x * 256 + threadIdx.x;
    int row = (int)(i / INNERP), col = (int)(i % INNERP);
    float r = 0.f;
    if (col < INNER) {
        const float* hr = h + (size_t)row * (2 * INNER);
        float v = hr[col];
        float g = hr[INNER + col];
        r = v * (g / (1.f + __expf(-g)));
    }
    u[i] = __float2bfloat16(r);
}

// ---------------- launch ----------------------------------------------------
extern "C" void kernel_launch(void* const* d_in, const int* in_sizes, int n_in,
                              void* d_out, int out_size)
{
    const float* tokens = (const float*)d_in[0];
    const float* cond   = (const float*)d_in[1];
    const float* w_qkv  = (const float*)d_in[2];
    const float* b_qkv  = (const float*)d_in[3];
    const float* w_ao   = (const float*)d_in[4];
    const float* b_ao   = (const float*)d_in[5];
    const float* w_fi   = (const float*)d_in[6];
    const float* b_fi   = (const float*)d_in[7];
    const float* w_fo   = (const float*)d_in[8];
    const float* b_fo   = (const float*)d_in[9];
    const float* w_mod  = (const float*)d_in[10];
    const float* b_mod  = (const float*)d_in[11];
    float* out = (float*)d_out;

    float *mod, *qkv, *proj, *tok2, *hbuf;
    __nv_bfloat16 *xb, *attnb, *ub, *wqkv_t, *wao_t, *wfi_t, *wfo_t;
    cudaGetSymbolAddress((void**)&mod,   g_mod);
    cudaGetSymbolAddress((void**)&qkv,   g_qkv);
    cudaGetSymbolAddress((void**)&proj,  g_proj);
    cudaGetSymbolAddress((void**)&tok2,  g_tok2);
    cudaGetSymbolAddress((void**)&hbuf,  g_h);
    cudaGetSymbolAddress((void**)&xb,    g_xb);
    cudaGetSymbolAddress((void**)&attnb, g_attnb);
    cudaGetSymbolAddress((void**)&ub,    g_ub);
    cudaGetSymbolAddress((void**)&wqkv_t, g_wqkv_t);
    cudaGetSymbolAddress((void**)&wao_t,  g_wao_t);
    cudaGetSymbolAddress((void**)&wfi_t,  g_wfi_t);
    cudaGetSymbolAddress((void**)&wfo_t,  g_wfo_t);

    cudaFuncSetAttribute(bf16_gemm_bias,
                         cudaFuncAttributeMaxDynamicSharedMemorySize, GSMEM);

    // Launch order puts the qkv GEMM at launch #6 so ncu (-s 5 -c 1)
    // captures it next round.
    // 0) weight transposes needed before qkv (wfo deferred to just-in-time)
    transpose_w<<<dim3(3 * DD / 32, DD / 32), 256>>>(w_qkv, wqkv_t, DD, 3 * DD, DD);   // 1
    transpose_w<<<dim3(DD / 32, DD / 32), 256>>>(w_ao, wao_t, DD, DD, DD);             // 2
    transpose_w<<<dim3(NFIP / 32, DD / 32), 256>>>(w_fi, wfi_t, DD, NFI, DD);          // 3
    // 1) modulation vector
    mod_kernel<<<dim3(MODW / 256, BB), 256>>>(cond, w_mod, b_mod, mod);                // 4
    // 2) x = modulate(LN(tokens)) -> bf16
    ln_mod_kernel<<<ROWS_TOT, 256>>>(tokens, mod, xb, 0, 1024);                        // 5
    // 3) qkv GEMM  == launch #6 (ncu target)
    bf16_gemm_bias<<<dim3(3 * DD / 128, ROWS_TOT / 128), 256, GSMEM>>>(
        xb, wqkv_t, b_qkv, qkv, 3 * DD, DD);                                           // 6
    // deferred transpose for ffn_out weights
    transpose_w<<<dim3(DD / 32, INNERP / 32), 256>>>(w_fo, wfo_t, INNER, DD, INNERP);  // 7
    // 4) rope + l2norm
    rope_l2_kernel<<<(BB * SS * HH * 2) / 8, 256>>>(qkv);
    // 5) attention -> bf16
    attn_kernel<<<BB * HH * (SS / 16), 512>>>(qkv, attnb);
    // 6) attn out projection
    bf16_gemm_bias<<<dim3(DD / 128, ROWS_TOT / 128), 256, GSMEM>>>(
        attnb, wao_t, b_ao, proj, DD, DD);
    // 7) tokens2 = tokens + gate_a * proj
    resgate_kernel<<<ROWS_TOT * DD / 256, 256>>>(tokens, proj, mod, 2048, tok2);
    // 8) y = modulate(LN(tokens2)) -> bf16 (reuse xb)
    ln_mod_kernel<<<ROWS_TOT, 256>>>(tok2, mod, xb, 3072, 4096);
    // 9) ffn_in, N=5460 (Bt padded to 5504 rows)
    bf16_gemm_bias<<<dim3(NFIP / 128, ROWS_TOT / 128), 256, GSMEM>>>(
        xb, wfi_t, b_fi, hbuf, NFI, DD);
    // 10) swiglu -> bf16 padded to 2752
    swiglu_kernel<<<(unsigned)(((size_t)ROWS_TOT * INNERP) / 256), 256>>>(hbuf, ub);
    // 11) ffn_out, K = 2752 (zero-padded)
    bf16_gemm_bias<<<dim3(DD / 128, ROWS_TOT / 128), 256, GSMEM>>>(
        ub, wfo_t, b_fo, proj, DD, INNERP);
    // 12) out = tokens2 + gate_m * proj
    resgate_kernel<<<ROWS_TOT * DD / 256, 256>>>(tok2, proj, mod, 5120, out);
}